// round 14
// baseline (speedup 1.0000x reference)
#include <cuda_runtime.h>
#include <cuda_bf16.h>
#include <mma.h>
#include <math.h>

using namespace nvcuda;

#define NB    4
#define SS    128
#define CDIM  256
#define NHH   4
#define DHH   32
#define NWIN  256
#define WSZ   64
#define MTOT  (NB*SS*SS)
#define NQKV  768
#define QSCALE 0.17677669529663687f

typedef unsigned long long ull;

// ---------------- scratch ----------------
__device__ float g_q  [MTOT * CDIM];
__device__ float g_kv [MTOT * 2 * CDIM];
__device__ __nv_bfloat16 g_xhi[MTOT * CDIM];
__device__ __nv_bfloat16 g_xlo[MTOT * CDIM];
__device__ __nv_bfloat16 g_ahi[MTOT * CDIM];
__device__ __nv_bfloat16 g_alo[MTOT * CDIM];
__device__ __nv_bfloat16 g_whi[CDIM * NQKV];
__device__ __nv_bfloat16 g_wlo[CDIM * NQKV];
__device__ __nv_bfloat16 g_wohi[CDIM * CDIM];
__device__ __nv_bfloat16 g_wolo[CDIM * CDIM];
__device__ float g_pos1t[NHH * WSZ * WSZ];
__device__ float g_pos2t[NHH * NWIN * NWIN];

// ---------------- helpers (no braces inside asm strings) ----------------
union F2U {
    float2 f;
    ull u;
};
__device__ __forceinline__ ull f2pack(float x, float y) {
    F2U t; t.f = make_float2(x, y); return t.u;
}
__device__ __forceinline__ float2 f2unpack(ull v) {
    F2U t; t.u = v; return t.f;
}
__device__ __forceinline__ ull ffma2(ull a, ull b, ull c) {
    ull d;
    asm("fma.rn.f32x2 %0,%1,%2,%3;" : "=l"(d) : "l"(a), "l"(b), "l"(c));
    return d;
}
__device__ __forceinline__ ull fmul2(ull a, ull b) {
    ull d;
    asm("mul.rn.f32x2 %0,%1,%2;" : "=l"(d) : "l"(a), "l"(b));
    return d;
}
__device__ __forceinline__ void split1(float x, __nv_bfloat16& h, __nv_bfloat16& l) {
    h = __float2bfloat16(x);
    l = __float2bfloat16(x - __bfloat162float(h));
}
__device__ __forceinline__ void cpasync16(void* s, const void* g) {
    unsigned saddr = (unsigned)__cvta_generic_to_shared(s);
    asm volatile("cp.async.cg.shared.global [%0], [%1], 16;" :: "r"(saddr), "l"(g));
}
__device__ __forceinline__ void cpcommit() {
    asm volatile("cp.async.commit_group;");
}
__device__ __forceinline__ void cpwait0() {
    asm volatile("cp.async.wait_group 0;");
}
__device__ __forceinline__ void cpwait1() {
    asm volatile("cp.async.wait_group 1;");
}

// ---------------- merged prep: pos transposes + weight splits ----------------
__global__ void prep_kernel(const float* __restrict__ p1,
                            const float* __restrict__ p2,
                            const float* __restrict__ Wq,
                            const float* __restrict__ Wkv,
                            const float* __restrict__ Wo) {
    int idx = blockIdx.x * blockDim.x + threadIdx.x;
    int stride = gridDim.x * blockDim.x;
    for (int i = idx; i < NHH * WSZ * WSZ; i += stride) {
        int hh = i / (WSZ * WSZ);
        int rem = i - hh * WSZ * WSZ;
        int r = rem / WSZ;
        int c = rem % WSZ;
        g_pos1t[(hh * WSZ + c) * WSZ + r] = p1[i];
    }
    for (int i = idx; i < NHH * NWIN * NWIN; i += stride) {
        int hh = i / (NWIN * NWIN);
        int rem = i - hh * NWIN * NWIN;
        int r = rem / NWIN;
        int c = rem % NWIN;
        g_pos2t[(hh * NWIN + c) * NWIN + r] = p2[i];
    }
    for (int i = idx; i < CDIM * CDIM; i += stride) {
        split1(Wo[i], g_wohi[i], g_wolo[i]);
    }
    for (int i = idx; i < CDIM * NQKV; i += stride) {
        int k = i / NQKV;
        int c = i % NQKV;
        float v = (c < 256) ? Wq[k * 256 + c] : Wkv[k * 512 + (c - 256)];
        split1(v, g_whi[i], g_wlo[i]);
    }
}

// ---------------- x split ----------------
__global__ void split_x(const float* __restrict__ src) {
    int idx = blockIdx.x * blockDim.x + threadIdx.x;
    int stride = gridDim.x * blockDim.x;
    const int n4 = MTOT * CDIM / 4;
    for (int i = idx; i < n4; i += stride) {
        float4 v = ((const float4*)src)[i];
        __nv_bfloat16 h4[4];
        __nv_bfloat16 l4[4];
        split1(v.x, h4[0], l4[0]);
        split1(v.y, h4[1], l4[1]);
        split1(v.z, h4[2], l4[2]);
        split1(v.w, h4[3], l4[3]);
        ((uint2*)g_xhi)[i] = *(uint2*)h4;
        ((uint2*)g_xlo)[i] = *(uint2*)l4;
    }
}

// ---------------- WMMA split-bf16 GEMM, cp.async double-buffered ------------
__device__ __forceinline__ int remap_row(int row) {
    int b = row >> 14;
    int n = (row >> 6) & 255;
    int m = row & 63;
    int h = ((n >> 4) << 3) + (m >> 3);
    int w = ((n & 15) << 3) + (m & 7);
    return (b << 14) + (h << 7) + w;
}

__global__ __launch_bounds__(256) void gemm_wmma(
    int mode, float* __restrict__ outp, const float* __restrict__ bo)
{
    const int Ntot = mode ? 256 : NQKV;
    const __nv_bfloat16* __restrict__ Ahi = mode ? g_ahi : g_xhi;
    const __nv_bfloat16* __restrict__ Alo = mode ? g_alo : g_xlo;
    const __nv_bfloat16* __restrict__ Bhi = mode ? g_wohi : g_whi;
    const __nv_bfloat16* __restrict__ Blo = mode ? g_wolo : g_wlo;

    __shared__ __align__(32) __nv_bfloat16 As[2][2][128][24];
    __shared__ __align__(32) __nv_bfloat16 Bs[2][2][16][136];

    const int tid = threadIdx.x;
    const int wid = tid >> 5;
    const int lane = tid & 31;
    const int nb0 = blockIdx.x * 128;
    const int mrow0 = blockIdx.y * 128;
    const int m0w = (wid & 3) * 32;
    const int n0w = (wid >> 2) * 64;

    wmma::fragment<wmma::accumulator, 16, 16, 16, float> cfrag[2][4];
#pragma unroll
    for (int mi = 0; mi < 2; mi++) {
#pragma unroll
        for (int ni = 0; ni < 4; ni++) {
            wmma::fill_fragment(cfrag[mi][ni], 0.0f);
        }
    }

    const int arow = tid >> 1;
    const int acol8 = (tid & 1) * 8;
    const int bkr = tid >> 4;
    const int bnc8 = (tid & 15) * 8;

    {
        cpasync16(&As[0][0][arow][acol8],
                  Ahi + (size_t)(mrow0 + arow) * 256 + acol8);
        cpasync16(&As[0][1][arow][acol8],
                  Alo + (size_t)(mrow0 + arow) * 256 + acol8);
        cpasync16(&Bs[0][0][bkr][bnc8],
                  Bhi + (size_t)(bkr) * Ntot + nb0 + bnc8);
        cpasync16(&Bs[0][1][bkr][bnc8],
                  Blo + (size_t)(bkr) * Ntot + nb0 + bnc8);
        cpcommit();
    }

    const int NT = 256 / 16;
    for (int t = 0; t < NT; t++) {
        int buf = t & 1;
        if (t + 1 < NT) {
            int kn = (t + 1) * 16;
            cpasync16(&As[1 - buf][0][arow][acol8],
                      Ahi + (size_t)(mrow0 + arow) * 256 + kn + acol8);
            cpasync16(&As[1 - buf][1][arow][acol8],
                      Alo + (size_t)(mrow0 + arow) * 256 + kn + acol8);
            cpasync16(&Bs[1 - buf][0][bkr][bnc8],
                      Bhi + (size_t)(kn + bkr) * Ntot + nb0 + bnc8);
            cpasync16(&Bs[1 - buf][1][bkr][bnc8],
                      Blo + (size_t)(kn + bkr) * Ntot + nb0 + bnc8);
            cpcommit();
            cpwait1();
        } else {
            cpwait0();
        }
        __syncthreads();

        wmma::fragment<wmma::matrix_a, 16, 16, 16, __nv_bfloat16, wmma::row_major> afh[2];
        wmma::fragment<wmma::matrix_a, 16, 16, 16, __nv_bfloat16, wmma::row_major> afl[2];
        wmma::load_matrix_sync(afh[0], &As[buf][0][m0w][0], 24);
        wmma::load_matrix_sync(afh[1], &As[buf][0][m0w + 16][0], 24);
        wmma::load_matrix_sync(afl[0], &As[buf][1][m0w][0], 24);
        wmma::load_matrix_sync(afl[1], &As[buf][1][m0w + 16][0], 24);
#pragma unroll
        for (int ni = 0; ni < 4; ni++) {
            wmma::fragment<wmma::matrix_b, 16, 16, 16, __nv_bfloat16, wmma::row_major> bfh;
            wmma::fragment<wmma::matrix_b, 16, 16, 16, __nv_bfloat16, wmma::row_major> bfl;
            wmma::load_matrix_sync(bfh, &Bs[buf][0][0][n0w + ni * 16], 136);
            wmma::load_matrix_sync(bfl, &Bs[buf][1][0][n0w + ni * 16], 136);
#pragma unroll
            for (int mi = 0; mi < 2; mi++) {
                wmma::mma_sync(cfrag[mi][ni], afh[mi], bfh, cfrag[mi][ni]);
                wmma::mma_sync(cfrag[mi][ni], afh[mi], bfl, cfrag[mi][ni]);
                wmma::mma_sync(cfrag[mi][ni], afl[mi], bfh, cfrag[mi][ni]);
            }
        }
        __syncthreads();
    }

    if (mode == 0) {
#pragma unroll
        for (int mi = 0; mi < 2; mi++) {
#pragma unroll
            for (int ni = 0; ni < 4; ni++) {
                int row = mrow0 + m0w + mi * 16;
                int col = nb0 + n0w + ni * 16;
                if (col < 256) {
#pragma unroll
                    for (int e = 0; e < cfrag[mi][ni].num_elements; e++) {
                        cfrag[mi][ni].x[e] *= QSCALE;
                    }
                    wmma::store_matrix_sync(g_q + (size_t)row * 256 + col,
                                            cfrag[mi][ni], 256, wmma::mem_row_major);
                } else {
                    wmma::store_matrix_sync(g_kv + (size_t)row * 512 + (col - 256),
                                            cfrag[mi][ni], 512, wmma::mem_row_major);
                }
            }
        }
    } else {
        float* stg = (float*)&As[0][0][0][0];
        float* mystg = stg + wid * 256;
#pragma unroll
        for (int mi = 0; mi < 2; mi++) {
#pragma unroll
            for (int ni = 0; ni < 4; ni++) {
                wmma::store_matrix_sync(mystg, cfrag[mi][ni], 16, wmma::mem_row_major);
                __syncwarp();
                int row0 = mrow0 + m0w + mi * 16;
                int col0 = nb0 + n0w + ni * 16;
#pragma unroll
                for (int e = 0; e < 8; e++) {
                    int idx = lane * 8 + e;
                    int r = idx >> 4;
                    int c = idx & 15;
                    int grow = remap_row(row0 + r);
                    outp[(size_t)grow * 256 + col0 + c] = mystg[r * 16 + c] + bo[col0 + c];
                }
                __syncwarp();
            }
        }
    }
}

// ---------------- attention branch 1: 2 windows per 128-thread block --------
__global__ __launch_bounds__(128, 6) void attn1_kernel() {
    int g  = blockIdx.x;              // window pair 0..127
    int hh = blockIdx.y;
    int b  = blockIdx.z;
    int wloc = threadIdx.x >> 6;      // 0..1
    int i  = threadIdx.x & 63;
    int n  = g * 2 + wloc;

    __shared__ float ks[2][WSZ][36];
    __shared__ float vs[2][WSZ][36];

    int h = ((n >> 4) << 3) + (i >> 3);
    int w = ((n & 15) << 3) + (i & 7);
    size_t grow = ((size_t)b << 14) + (h << 7) + w;

    {
        const float4* kp = (const float4*)(g_kv + grow * 512 + hh * DHH);
        const float4* vp = (const float4*)(g_kv + grow * 512 + 256 + hh * DHH);
#pragma unroll
        for (int d4 = 0; d4 < 8; d4++) {
            *(float4*)(&ks[wloc][i][d4 * 4]) = kp[d4];
            *(float4*)(&vs[wloc][i][d4 * 4]) = vp[d4];
        }
    }
    ull qr2[16];
    {
        const ulonglong2* qp = (const ulonglong2*)(g_q + grow * 256 + hh * DHH);
#pragma unroll
        for (int d4 = 0; d4 < 8; d4++) {
            ulonglong2 q4 = qp[d4];
            qr2[2 * d4]     = q4.x;
            qr2[2 * d4 + 1] = q4.y;
        }
    }
    __syncthreads();

    const float* pos = g_pos1t + hh * WSZ * WSZ;
    float mrun = -INFINITY;
    float l = 0.f;
    ull acc2[16];
#pragma unroll
    for (int t = 0; t < 16; t++) acc2[t] = 0ULL;

#pragma unroll 2
    for (int j = 0; j < WSZ; j++) {
        float pb = pos[j * WSZ + i];
        const ulonglong2* kp2 = (const ulonglong2*)(&ks[wloc][j][0]);
        ull sA = 0ULL;
        ull sB = 0ULL;
        ull sC = 0ULL;
        ull sD = 0ULL;
#pragma unroll
        for (int t = 0; t < 4; t++) {
            ulonglong2 k0 = kp2[t];
            ulonglong2 k1 = kp2[t + 4];
            sA = ffma2(qr2[2 * t],     k0.x, sA);
            sB = ffma2(qr2[2 * t + 1], k0.y, sB);
            sC = ffma2(qr2[2 * t + 8], k1.x, sC);
            sD = ffma2(qr2[2 * t + 9], k1.y, sD);
        }
        float2 a = f2unpack(sA);
        float2 bb = f2unpack(sB);
        float2 cc = f2unpack(sC);
        float2 dd = f2unpack(sD);
        float s = ((a.x + a.y) + (bb.x + bb.y)) + ((cc.x + cc.y) + (dd.x + dd.y)) + pb;
        if (s > mrun) {
            float c = __expf(mrun - s);
            mrun = s;
            l *= c;
            ull cc2 = f2pack(c, c);
#pragma unroll
            for (int t = 0; t < 16; t++) acc2[t] = fmul2(acc2[t], cc2);
        }
        float p = __expf(s - mrun);
        l += p;
        ull pp2 = f2pack(p, p);
        const ulonglong2* vp2 = (const ulonglong2*)(&vs[wloc][j][0]);
#pragma unroll
        for (int t = 0; t < 8; t++) {
            ulonglong2 vv = vp2[t];
            acc2[2 * t]     = ffma2(pp2, vv.x, acc2[2 * t]);
            acc2[2 * t + 1] = ffma2(pp2, vv.y, acc2[2 * t + 1]);
        }
    }
    float inv = 1.f / l;
    size_t obase = (((size_t)(b * NWIN + n) * WSZ) + i) * CDIM + hh * DHH;
#pragma unroll
    for (int t = 0; t < 8; t++) {
        float2 p0 = f2unpack(acc2[2 * t]);
        float2 p1 = f2unpack(acc2[2 * t + 1]);
        __nv_bfloat16 h4[4];
        __nv_bfloat16 l4[4];
        split1(p0.x * inv, h4[0], l4[0]);
        split1(p0.y * inv, h4[1], l4[1]);
        split1(p1.x * inv, h4[2], l4[2]);
        split1(p1.y * inv, h4[3], l4[3]);
        *(uint2*)(g_ahi + obase + t * 4) = *(uint2*)h4;
        *(uint2*)(g_alo + obase + t * 4) = *(uint2*)l4;
    }
}

// ---------------- attention branch 2 (cross-window, seq=256) ----------------
__global__ __launch_bounds__(256, 3) void attn2_kernel() {
    int m  = blockIdx.x;
    int hh = blockIdx.y;
    int b  = blockIdx.z;
    int i  = threadIdx.x;

    __shared__ float ks[128][36];
    __shared__ float vs[128][36];

    int h = ((i >> 4) << 3) + (m >> 3);
    int w = ((i & 15) << 3) + (m & 7);
    size_t grow = ((size_t)b << 14) + (h << 7) + w;

    ull qr2[16];
    {
        const ulonglong2* qp = (const ulonglong2*)(g_q + grow * 256 + 128 + hh * DHH);
#pragma unroll
        for (int d4 = 0; d4 < 8; d4++) {
            ulonglong2 q4 = qp[d4];
            qr2[2 * d4]     = q4.x;
            qr2[2 * d4 + 1] = q4.y;
        }
    }

    const float* pos = g_pos2t + hh * NWIN * NWIN;
    float mrun = -INFINITY;
    float l = 0.f;
    ull acc2[16];
#pragma unroll
    for (int t = 0; t < 16; t++) acc2[t] = 0ULL;

    for (int jc = 0; jc < NWIN; jc += 128) {
        __syncthreads();
        {
            int t = threadIdx.x;
            int r = t & 127;
            int jw = jc + r;
            int hK = ((jw >> 4) << 3) + (m >> 3);
            int wK = ((jw & 15) << 3) + (m & 7);
            size_t gk = ((size_t)b << 14) + (hK << 7) + wK;
            if (t < 128) {
                const float4* kp = (const float4*)(g_kv + gk * 512 + 128 + hh * DHH);
#pragma unroll
                for (int d4 = 0; d4 < 8; d4++) *(float4*)(&ks[r][d4 * 4]) = kp[d4];
            } else {
                const float4* vp = (const float4*)(g_kv + gk * 512 + 384 + hh * DHH);
#pragma unroll
                for (int d4 = 0; d4 < 8; d4++) *(float4*)(&vs[r][d4 * 4]) = vp[d4];
            }
        }
        __syncthreads();

#pragma unroll 2
        for (int jj = 0; jj < 128; jj++) {
            float pb = pos[(jc + jj) * NWIN + i];
            const ulonglong2* kp2 = (const ulonglong2*)(&ks[jj][0]);
            ull sA = 0ULL;
            ull sB = 0ULL;
            ull sC = 0ULL;
            ull sD = 0ULL;
#pragma unroll
            for (int t = 0; t < 4; t++) {
                ulonglong2 k0 = kp2[t];
                ulonglong2 k1 = kp2[t + 4];
                sA = ffma2(qr2[2 * t],     k0.x, sA);
                sB = ffma2(qr2[2 * t + 1], k0.y, sB);
                sC = ffma2(qr2[2 * t + 8], k1.x, sC);
                sD = ffma2(qr2[2 * t + 9], k1.y, sD);
            }
            float2 a = f2unpack(sA);
            float2 bb = f2unpack(sB);
            float2 cc = f2unpack(sC);
            float2 dd = f2unpack(sD);
            float s = ((a.x + a.y) + (bb.x + bb.y)) + ((cc.x + cc.y) + (dd.x + dd.y)) + pb;
            if (s > mrun) {
                float c = __expf(mrun - s);
                mrun = s;
                l *= c;
                ull cc2 = f2pack(c, c);
#pragma unroll
                for (int t = 0; t < 16; t++) acc2[t] = fmul2(acc2[t], cc2);
            }
            float p = __expf(s - mrun);
            l += p;
            ull pp2 = f2pack(p, p);
            const ulonglong2* vp2 = (const ulonglong2*)(&vs[jj][0]);
#pragma unroll
            for (int t = 0; t < 8; t++) {
                ulonglong2 vv = vp2[t];
                acc2[2 * t]     = ffma2(pp2, vv.x, acc2[2 * t]);
                acc2[2 * t + 1] = ffma2(pp2, vv.y, acc2[2 * t + 1]);
            }
        }
    }
    float inv = 1.f / l;
    size_t obase = (((size_t)(b * NWIN + i) * WSZ) + m) * CDIM + 128 + hh * DHH;
#pragma unroll
    for (int t = 0; t < 8; t++) {
        float2 p0 = f2unpack(acc2[2 * t]);
        float2 p1 = f2unpack(acc2[2 * t + 1]);
        __nv_bfloat16 h4[4];
        __nv_bfloat16 l4[4];
        split1(p0.x * inv, h4[0], l4[0]);
        split1(p0.y * inv, h4[1], l4[1]);
        split1(p1.x * inv, h4[2], l4[2]);
        split1(p1.y * inv, h4[3], l4[3]);
        *(uint2*)(g_ahi + obase + t * 4) = *(uint2*)h4;
        *(uint2*)(g_alo + obase + t * 4) = *(uint2*)l4;
    }
}

// ---------------------------------------------------------------------------
extern "C" void kernel_launch(void* const* d_in, const int* in_sizes, int n_in,
                              void* d_out, int out_size) {
    const float* x   = (const float*)d_in[0];
    const float* Wq  = (const float*)d_in[1];
    const float* Wkv = (const float*)d_in[2];
    const float* Wo  = (const float*)d_in[3];
    const float* bo  = (const float*)d_in[4];
    const float* p1  = (const float*)d_in[5];
    const float* p2  = (const float*)d_in[6];
    float* out = (float*)d_out;

    prep_kernel<<<768, 256>>>(p1, p2, Wq, Wkv, Wo);
    split_x<<<2048, 256>>>(x);
    gemm_wmma<<<dim3(6, 512), 256>>>(0, (float*)0, (const float*)0);
    attn1_kernel<<<dim3(128, 4, 4), 128>>>();
    attn2_kernel<<<dim3(64, 4, 4), 256>>>();
    gemm_wmma<<<dim3(2, 512), 256>>>(1, out, bo);
}

// round 15
// speedup vs baseline: 1.5673x; 1.5673x over previous
#include <cuda_runtime.h>
#include <cuda_bf16.h>
#include <mma.h>
#include <math.h>

using namespace nvcuda;

#define NB    4
#define SS    128
#define CDIM  256
#define NHH   4
#define DHH   32
#define NWIN  256
#define WSZ   64
#define MTOT  (NB*SS*SS)
#define NQKV  768
#define QSCALE 0.17677669529663687f

typedef unsigned long long ull;

// ---------------- scratch ----------------
__device__ float g_q  [MTOT * CDIM];
__device__ float g_kv [MTOT * 2 * CDIM];
__device__ __nv_bfloat16 g_xhi[MTOT * CDIM];
__device__ __nv_bfloat16 g_xlo[MTOT * CDIM];
__device__ __nv_bfloat16 g_ahi[MTOT * CDIM];
__device__ __nv_bfloat16 g_alo[MTOT * CDIM];
__device__ __nv_bfloat16 g_whi[CDIM * NQKV];
__device__ __nv_bfloat16 g_wlo[CDIM * NQKV];
__device__ __nv_bfloat16 g_wohi[CDIM * CDIM];
__device__ __nv_bfloat16 g_wolo[CDIM * CDIM];
__device__ float g_pos1t[NHH * WSZ * WSZ];
__device__ float g_pos2t[NHH * NWIN * NWIN];

// ---------------- helpers (no braces inside asm strings) ----------------
union F2U {
    float2 f;
    ull u;
};
__device__ __forceinline__ ull f2pack(float x, float y) {
    F2U t; t.f = make_float2(x, y); return t.u;
}
__device__ __forceinline__ float2 f2unpack(ull v) {
    F2U t; t.u = v; return t.f;
}
__device__ __forceinline__ ull ffma2(ull a, ull b, ull c) {
    ull d;
    asm("fma.rn.f32x2 %0,%1,%2,%3;" : "=l"(d) : "l"(a), "l"(b), "l"(c));
    return d;
}
__device__ __forceinline__ ull fmul2(ull a, ull b) {
    ull d;
    asm("mul.rn.f32x2 %0,%1,%2;" : "=l"(d) : "l"(a), "l"(b));
    return d;
}
__device__ __forceinline__ void split1(float x, __nv_bfloat16& h, __nv_bfloat16& l) {
    h = __float2bfloat16(x);
    l = __float2bfloat16(x - __bfloat162float(h));
}
__device__ __forceinline__ void cpasync16(void* s, const void* g) {
    unsigned saddr = (unsigned)__cvta_generic_to_shared(s);
    asm volatile("cp.async.cg.shared.global [%0], [%1], 16;" :: "r"(saddr), "l"(g));
}
__device__ __forceinline__ void cpcommit() {
    asm volatile("cp.async.commit_group;");
}
__device__ __forceinline__ void cpwait0() {
    asm volatile("cp.async.wait_group 0;");
}
__device__ __forceinline__ void cpwait1() {
    asm volatile("cp.async.wait_group 1;");
}

// ---------------- merged prep: pos transposes + weight splits ----------------
__global__ void prep_kernel(const float* __restrict__ p1,
                            const float* __restrict__ p2,
                            const float* __restrict__ Wq,
                            const float* __restrict__ Wkv,
                            const float* __restrict__ Wo) {
    int idx = blockIdx.x * blockDim.x + threadIdx.x;
    int stride = gridDim.x * blockDim.x;
    for (int i = idx; i < NHH * WSZ * WSZ; i += stride) {
        int hh = i / (WSZ * WSZ);
        int rem = i - hh * WSZ * WSZ;
        int r = rem / WSZ;
        int c = rem % WSZ;
        g_pos1t[(hh * WSZ + c) * WSZ + r] = p1[i];
    }
    for (int i = idx; i < NHH * NWIN * NWIN; i += stride) {
        int hh = i / (NWIN * NWIN);
        int rem = i - hh * NWIN * NWIN;
        int r = rem / NWIN;
        int c = rem % NWIN;
        g_pos2t[(hh * NWIN + c) * NWIN + r] = p2[i];
    }
    for (int i = idx; i < CDIM * CDIM; i += stride) {
        split1(Wo[i], g_wohi[i], g_wolo[i]);
    }
    for (int i = idx; i < CDIM * NQKV; i += stride) {
        int k = i / NQKV;
        int c = i % NQKV;
        float v = (c < 256) ? Wq[k * 256 + c] : Wkv[k * 512 + (c - 256)];
        split1(v, g_whi[i], g_wlo[i]);
    }
}

// ---------------- x split ----------------
__global__ void split_x(const float* __restrict__ src) {
    int idx = blockIdx.x * blockDim.x + threadIdx.x;
    int stride = gridDim.x * blockDim.x;
    const int n4 = MTOT * CDIM / 4;
    for (int i = idx; i < n4; i += stride) {
        float4 v = ((const float4*)src)[i];
        __nv_bfloat16 h4[4];
        __nv_bfloat16 l4[4];
        split1(v.x, h4[0], l4[0]);
        split1(v.y, h4[1], l4[1]);
        split1(v.z, h4[2], l4[2]);
        split1(v.w, h4[3], l4[3]);
        ((uint2*)g_xhi)[i] = *(uint2*)h4;
        ((uint2*)g_xlo)[i] = *(uint2*)l4;
    }
}

// ---------------- WMMA split-bf16 GEMM, cp.async double-buffered ------------
__device__ __forceinline__ int remap_row(int row) {
    int b = row >> 14;
    int n = (row >> 6) & 255;
    int m = row & 63;
    int h = ((n >> 4) << 3) + (m >> 3);
    int w = ((n & 15) << 3) + (m & 7);
    return (b << 14) + (h << 7) + w;
}

__global__ __launch_bounds__(256) void gemm_wmma(
    int mode, float* __restrict__ outp, const float* __restrict__ bo)
{
    const int Ntot = mode ? 256 : NQKV;
    const __nv_bfloat16* __restrict__ Ahi = mode ? g_ahi : g_xhi;
    const __nv_bfloat16* __restrict__ Alo = mode ? g_alo : g_xlo;
    const __nv_bfloat16* __restrict__ Bhi = mode ? g_wohi : g_whi;
    const __nv_bfloat16* __restrict__ Blo = mode ? g_wolo : g_wlo;

    __shared__ __align__(32) __nv_bfloat16 As[2][2][128][24];
    __shared__ __align__(32) __nv_bfloat16 Bs[2][2][16][136];

    const int tid = threadIdx.x;
    const int wid = tid >> 5;
    const int lane = tid & 31;
    const int nb0 = blockIdx.x * 128;
    const int mrow0 = blockIdx.y * 128;
    const int m0w = (wid & 3) * 32;
    const int n0w = (wid >> 2) * 64;

    wmma::fragment<wmma::accumulator, 16, 16, 16, float> cfrag[2][4];
#pragma unroll
    for (int mi = 0; mi < 2; mi++) {
#pragma unroll
        for (int ni = 0; ni < 4; ni++) {
            wmma::fill_fragment(cfrag[mi][ni], 0.0f);
        }
    }

    const int arow = tid >> 1;
    const int acol8 = (tid & 1) * 8;
    const int bkr = tid >> 4;
    const int bnc8 = (tid & 15) * 8;

    {
        cpasync16(&As[0][0][arow][acol8],
                  Ahi + (size_t)(mrow0 + arow) * 256 + acol8);
        cpasync16(&As[0][1][arow][acol8],
                  Alo + (size_t)(mrow0 + arow) * 256 + acol8);
        cpasync16(&Bs[0][0][bkr][bnc8],
                  Bhi + (size_t)(bkr) * Ntot + nb0 + bnc8);
        cpasync16(&Bs[0][1][bkr][bnc8],
                  Blo + (size_t)(bkr) * Ntot + nb0 + bnc8);
        cpcommit();
    }

    const int NT = 256 / 16;
    for (int t = 0; t < NT; t++) {
        int buf = t & 1;
        if (t + 1 < NT) {
            int kn = (t + 1) * 16;
            cpasync16(&As[1 - buf][0][arow][acol8],
                      Ahi + (size_t)(mrow0 + arow) * 256 + kn + acol8);
            cpasync16(&As[1 - buf][1][arow][acol8],
                      Alo + (size_t)(mrow0 + arow) * 256 + kn + acol8);
            cpasync16(&Bs[1 - buf][0][bkr][bnc8],
                      Bhi + (size_t)(kn + bkr) * Ntot + nb0 + bnc8);
            cpasync16(&Bs[1 - buf][1][bkr][bnc8],
                      Blo + (size_t)(kn + bkr) * Ntot + nb0 + bnc8);
            cpcommit();
            cpwait1();
        } else {
            cpwait0();
        }
        __syncthreads();

        wmma::fragment<wmma::matrix_a, 16, 16, 16, __nv_bfloat16, wmma::row_major> afh[2];
        wmma::fragment<wmma::matrix_a, 16, 16, 16, __nv_bfloat16, wmma::row_major> afl[2];
        wmma::load_matrix_sync(afh[0], &As[buf][0][m0w][0], 24);
        wmma::load_matrix_sync(afh[1], &As[buf][0][m0w + 16][0], 24);
        wmma::load_matrix_sync(afl[0], &As[buf][1][m0w][0], 24);
        wmma::load_matrix_sync(afl[1], &As[buf][1][m0w + 16][0], 24);
#pragma unroll
        for (int ni = 0; ni < 4; ni++) {
            wmma::fragment<wmma::matrix_b, 16, 16, 16, __nv_bfloat16, wmma::row_major> bfh;
            wmma::fragment<wmma::matrix_b, 16, 16, 16, __nv_bfloat16, wmma::row_major> bfl;
            wmma::load_matrix_sync(bfh, &Bs[buf][0][0][n0w + ni * 16], 136);
            wmma::load_matrix_sync(bfl, &Bs[buf][1][0][n0w + ni * 16], 136);
#pragma unroll
            for (int mi = 0; mi < 2; mi++) {
                wmma::mma_sync(cfrag[mi][ni], afh[mi], bfh, cfrag[mi][ni]);
                wmma::mma_sync(cfrag[mi][ni], afh[mi], bfl, cfrag[mi][ni]);
                wmma::mma_sync(cfrag[mi][ni], afl[mi], bfh, cfrag[mi][ni]);
            }
        }
        __syncthreads();
    }

    if (mode == 0) {
#pragma unroll
        for (int mi = 0; mi < 2; mi++) {
#pragma unroll
            for (int ni = 0; ni < 4; ni++) {
                int row = mrow0 + m0w + mi * 16;
                int col = nb0 + n0w + ni * 16;
                if (col < 256) {
#pragma unroll
                    for (int e = 0; e < cfrag[mi][ni].num_elements; e++) {
                        cfrag[mi][ni].x[e] *= QSCALE;
                    }
                    wmma::store_matrix_sync(g_q + (size_t)row * 256 + col,
                                            cfrag[mi][ni], 256, wmma::mem_row_major);
                } else {
                    wmma::store_matrix_sync(g_kv + (size_t)row * 512 + (col - 256),
                                            cfrag[mi][ni], 512, wmma::mem_row_major);
                }
            }
        }
    } else {
        float* stg = (float*)&As[0][0][0][0];
        float* mystg = stg + wid * 256;
#pragma unroll
        for (int mi = 0; mi < 2; mi++) {
#pragma unroll
            for (int ni = 0; ni < 4; ni++) {
                wmma::store_matrix_sync(mystg, cfrag[mi][ni], 16, wmma::mem_row_major);
                __syncwarp();
                int row0 = mrow0 + m0w + mi * 16;
                int col0 = nb0 + n0w + ni * 16;
#pragma unroll
                for (int e = 0; e < 8; e++) {
                    int idx = lane * 8 + e;
                    int r = idx >> 4;
                    int c = idx & 15;
                    int grow = remap_row(row0 + r);
                    outp[(size_t)grow * 256 + col0 + c] = mystg[r * 16 + c] + bo[col0 + c];
                }
                __syncwarp();
            }
        }
    }
}

// ---------------- attention branch 1 (within-window, seq=64) ----------------
// thread = (query pair qloc, qloc+32) x (channel half ch). 64 threads/window.
__global__ __launch_bounds__(64) void attn1_kernel() {
    int n  = blockIdx.x;
    int hh = blockIdx.y;
    int b  = blockIdx.z;
    int t  = threadIdx.x;
    int qloc = t >> 1;            // 0..31
    int ch   = t & 1;             // channel half

    __shared__ float ks[WSZ][36];
    __shared__ float vs[WSZ][36];

    // K/V row load: thread t owns key row t
    {
        int i = t;
        int h = ((n >> 4) << 3) + (i >> 3);
        int w = ((n & 15) << 3) + (i & 7);
        size_t gk = ((size_t)b << 14) + (h << 7) + w;
        const float4* kp = (const float4*)(g_kv + gk * 512 + hh * DHH);
        const float4* vp = (const float4*)(g_kv + gk * 512 + 256 + hh * DHH);
#pragma unroll
        for (int d4 = 0; d4 < 8; d4++) {
            *(float4*)(&ks[i][d4 * 4]) = kp[d4];
            *(float4*)(&vs[i][d4 * 4]) = vp[d4];
        }
    }

    // query rows i1, i2; load ch's 16 dims each (q pre-scaled by QSCALE)
    int i1 = qloc;
    int i2 = qloc + 32;
    int h1 = ((i1 >> 4) << 3) + (i1 >> 3 & 0);   // placeholder, recompute below
    // proper mapping
    h1 = ((n >> 4) << 3) + (i1 >> 3);
    int w1 = ((n & 15) << 3) + (i1 & 7);
    int h2 = ((n >> 4) << 3) + (i2 >> 3);
    int w2 = ((n & 15) << 3) + (i2 & 7);
    size_t gq1 = ((size_t)b << 14) + (h1 << 7) + w1;
    size_t gq2 = ((size_t)b << 14) + (h2 << 7) + w2;

    ull q1r[8];
    ull q2r[8];
    {
        const ulonglong2* qp1 = (const ulonglong2*)(g_q + gq1 * 256 + hh * DHH + ch * 16);
        const ulonglong2* qp2 = (const ulonglong2*)(g_q + gq2 * 256 + hh * DHH + ch * 16);
#pragma unroll
        for (int d = 0; d < 4; d++) {
            ulonglong2 a = qp1[d];
            q1r[2 * d]     = a.x;
            q1r[2 * d + 1] = a.y;
            ulonglong2 c = qp2[d];
            q2r[2 * d]     = c.x;
            q2r[2 * d + 1] = c.y;
        }
    }
    __syncthreads();

    const float* pos = g_pos1t + hh * WSZ * WSZ;
    float m1 = -INFINITY;
    float m2 = -INFINITY;
    float l1 = 0.f;
    float l2 = 0.f;
    ull acc1[8];
    ull acc2q[8];
#pragma unroll
    for (int d = 0; d < 8; d++) {
        acc1[d] = 0ULL;
        acc2q[d] = 0ULL;
    }

#pragma unroll 2
    for (int j = 0; j < WSZ; j++) {
        float pb1 = pos[j * WSZ + i1];
        float pb2 = pos[j * WSZ + i2];
        const ulonglong2* kp2 = (const ulonglong2*)(&ks[j][ch * 16]);
        ull s1a = 0ULL;
        ull s1b = 0ULL;
        ull s2a = 0ULL;
        ull s2b = 0ULL;
#pragma unroll
        for (int d = 0; d < 4; d++) {
            ulonglong2 kk = kp2[d];
            s1a = ffma2(q1r[2 * d],     kk.x, s1a);
            s1b = ffma2(q1r[2 * d + 1], kk.y, s1b);
            s2a = ffma2(q2r[2 * d],     kk.x, s2a);
            s2b = ffma2(q2r[2 * d + 1], kk.y, s2b);
        }
        float2 u1 = f2unpack(s1a);
        float2 w1v = f2unpack(s1b);
        float2 u2 = f2unpack(s2a);
        float2 w2v = f2unpack(s2b);
        float sh1 = (u1.x + u1.y) + (w1v.x + w1v.y);
        float sh2 = (u2.x + u2.y) + (w2v.x + w2v.y);
        sh1 += __shfl_xor_sync(0xffffffffu, sh1, 1);
        sh2 += __shfl_xor_sync(0xffffffffu, sh2, 1);
        float s1 = sh1 + pb1;
        float s2 = sh2 + pb2;

        if (s1 > m1) {
            float c = __expf(m1 - s1);
            m1 = s1;
            l1 *= c;
            ull cc = f2pack(c, c);
#pragma unroll
            for (int d = 0; d < 8; d++) acc1[d] = fmul2(acc1[d], cc);
        }
        if (s2 > m2) {
            float c = __expf(m2 - s2);
            m2 = s2;
            l2 *= c;
            ull cc = f2pack(c, c);
#pragma unroll
            for (int d = 0; d < 8; d++) acc2q[d] = fmul2(acc2q[d], cc);
        }
        float p1 = __expf(s1 - m1);
        float p2 = __expf(s2 - m2);
        l1 += p1;
        l2 += p2;
        ull p12 = f2pack(p1, p1);
        ull p22 = f2pack(p2, p2);
        const ulonglong2* vp2 = (const ulonglong2*)(&vs[j][ch * 16]);
#pragma unroll
        for (int d = 0; d < 4; d++) {
            ulonglong2 vv = vp2[d];
            acc1[2 * d]      = ffma2(p12, vv.x, acc1[2 * d]);
            acc1[2 * d + 1]  = ffma2(p12, vv.y, acc1[2 * d + 1]);
            acc2q[2 * d]     = ffma2(p22, vv.x, acc2q[2 * d]);
            acc2q[2 * d + 1] = ffma2(p22, vv.y, acc2q[2 * d + 1]);
        }
    }

    float inv1 = 1.f / l1;
    float inv2 = 1.f / l2;
    size_t ob1 = (((size_t)(b * NWIN + n) * WSZ) + i1) * CDIM + hh * DHH + ch * 16;
    size_t ob2 = (((size_t)(b * NWIN + n) * WSZ) + i2) * CDIM + hh * DHH + ch * 16;
#pragma unroll
    for (int d = 0; d < 4; d++) {
        float2 p0 = f2unpack(acc1[2 * d]);
        float2 p1 = f2unpack(acc1[2 * d + 1]);
        __nv_bfloat16 h4[4];
        __nv_bfloat16 l4[4];
        split1(p0.x * inv1, h4[0], l4[0]);
        split1(p0.y * inv1, h4[1], l4[1]);
        split1(p1.x * inv1, h4[2], l4[2]);
        split1(p1.y * inv1, h4[3], l4[3]);
        *(uint2*)(g_ahi + ob1 + d * 4) = *(uint2*)h4;
        *(uint2*)(g_alo + ob1 + d * 4) = *(uint2*)l4;
        float2 r0 = f2unpack(acc2q[2 * d]);
        float2 r1 = f2unpack(acc2q[2 * d + 1]);
        split1(r0.x * inv2, h4[0], l4[0]);
        split1(r0.y * inv2, h4[1], l4[1]);
        split1(r1.x * inv2, h4[2], l4[2]);
        split1(r1.y * inv2, h4[3], l4[3]);
        *(uint2*)(g_ahi + ob2 + d * 4) = *(uint2*)h4;
        *(uint2*)(g_alo + ob2 + d * 4) = *(uint2*)l4;
    }
}

// ---------------- attention branch 2 (cross-window, seq=256) ----------------
// thread = (query pair qloc, qloc+128) x (channel half ch). 256 threads.
__global__ __launch_bounds__(256) void attn2_kernel() {
    int m  = blockIdx.x;
    int hh = blockIdx.y;
    int b  = blockIdx.z;
    int t  = threadIdx.x;
    int qloc = t >> 1;            // 0..127
    int ch   = t & 1;

    __shared__ float ks[128][36];
    __shared__ float vs[128][36];

    int i1 = qloc;
    int i2 = qloc + 128;
    int h1 = ((i1 >> 4) << 3) + (m >> 3);
    int w1 = ((i1 & 15) << 3) + (m & 7);
    int h2 = ((i2 >> 4) << 3) + (m >> 3);
    int w2 = ((i2 & 15) << 3) + (m & 7);
    size_t gq1 = ((size_t)b << 14) + (h1 << 7) + w1;
    size_t gq2 = ((size_t)b << 14) + (h2 << 7) + w2;

    ull q1r[8];
    ull q2r[8];
    {
        const ulonglong2* qp1 = (const ulonglong2*)(g_q + gq1 * 256 + 128 + hh * DHH + ch * 16);
        const ulonglong2* qp2 = (const ulonglong2*)(g_q + gq2 * 256 + 128 + hh * DHH + ch * 16);
#pragma unroll
        for (int d = 0; d < 4; d++) {
            ulonglong2 a = qp1[d];
            q1r[2 * d]     = a.x;
            q1r[2 * d + 1] = a.y;
            ulonglong2 c = qp2[d];
            q2r[2 * d]     = c.x;
            q2r[2 * d + 1] = c.y;
        }
    }

    const float* pos = g_pos2t + hh * NWIN * NWIN;
    float m1 = -INFINITY;
    float m2 = -INFINITY;
    float l1 = 0.f;
    float l2 = 0.f;
    ull acc1[8];
    ull acc2q[8];
#pragma unroll
    for (int d = 0; d < 8; d++) {
        acc1[d] = 0ULL;
        acc2q[d] = 0ULL;
    }

    for (int jc = 0; jc < NWIN; jc += 128) {
        __syncthreads();
        {
            int r = t & 127;
            int jw = jc + r;
            int hK = ((jw >> 4) << 3) + (m >> 3);
            int wK = ((jw & 15) << 3) + (m & 7);
            size_t gk = ((size_t)b << 14) + (hK << 7) + wK;
            if (t < 128) {
                const float4* kp = (const float4*)(g_kv + gk * 512 + 128 + hh * DHH);
#pragma unroll
                for (int d4 = 0; d4 < 8; d4++) *(float4*)(&ks[r][d4 * 4]) = kp[d4];
            } else {
                const float4* vp = (const float4*)(g_kv + gk * 512 + 384 + hh * DHH);
#pragma unroll
                for (int d4 = 0; d4 < 8; d4++) *(float4*)(&vs[r][d4 * 4]) = vp[d4];
            }
        }
        __syncthreads();

#pragma unroll 2
        for (int jj = 0; jj < 128; jj++) {
            int j = jc + jj;
            float pb1 = pos[j * NWIN + i1];
            float pb2 = pos[j * NWIN + i2];
            const ulonglong2* kp2 = (const ulonglong2*)(&ks[jj][ch * 16]);
            ull s1a = 0ULL;
            ull s1b = 0ULL;
            ull s2a = 0ULL;
            ull s2b = 0ULL;
#pragma unroll
            for (int d = 0; d < 4; d++) {
                ulonglong2 kk = kp2[d];
                s1a = ffma2(q1r[2 * d],     kk.x, s1a);
                s1b = ffma2(q1r[2 * d + 1], kk.y, s1b);
                s2a = ffma2(q2r[2 * d],     kk.x, s2a);
                s2b = ffma2(q2r[2 * d + 1], kk.y, s2b);
            }
            float2 u1 = f2unpack(s1a);
            float2 w1v = f2unpack(s1b);
            float2 u2 = f2unpack(s2a);
            float2 w2v = f2unpack(s2b);
            float sh1 = (u1.x + u1.y) + (w1v.x + w1v.y);
            float sh2 = (u2.x + u2.y) + (w2v.x + w2v.y);
            sh1 += __shfl_xor_sync(0xffffffffu, sh1, 1);
            sh2 += __shfl_xor_sync(0xffffffffu, sh2, 1);
            float s1 = sh1 + pb1;
            float s2 = sh2 + pb2;

            if (s1 > m1) {
                float c = __expf(m1 - s1);
                m1 = s1;
                l1 *= c;
                ull cc = f2pack(c, c);
#pragma unroll
                for (int d = 0; d < 8; d++) acc1[d] = fmul2(acc1[d], cc);
            }
            if (s2 > m2) {
                float c = __expf(m2 - s2);
                m2 = s2;
                l2 *= c;
                ull cc = f2pack(c, c);
#pragma unroll
                for (int d = 0; d < 8; d++) acc2q[d] = fmul2(acc2q[d], cc);
            }
            float p1 = __expf(s1 - m1);
            float p2 = __expf(s2 - m2);
            l1 += p1;
            l2 += p2;
            ull p12 = f2pack(p1, p1);
            ull p22 = f2pack(p2, p2);
            const ulonglong2* vp2 = (const ulonglong2*)(&vs[jj][ch * 16]);
#pragma unroll
            for (int d = 0; d < 4; d++) {
                ulonglong2 vv = vp2[d];
                acc1[2 * d]      = ffma2(p12, vv.x, acc1[2 * d]);
                acc1[2 * d + 1]  = ffma2(p12, vv.y, acc1[2 * d + 1]);
                acc2q[2 * d]     = ffma2(p22, vv.x, acc2q[2 * d]);
                acc2q[2 * d + 1] = ffma2(p22, vv.y, acc2q[2 * d + 1]);
            }
        }
    }

    float inv1 = 1.f / l1;
    float inv2 = 1.f / l2;
    size_t ob1 = (((size_t)(b * NWIN + i1) * WSZ) + m) * CDIM + 128 + hh * DHH + ch * 16;
    size_t ob2 = (((size_t)(b * NWIN + i2) * WSZ) + m) * CDIM + 128 + hh * DHH + ch * 16;
#pragma unroll
    for (int d = 0; d < 4; d++) {
        float2 p0 = f2unpack(acc1[2 * d]);
        float2 p1 = f2unpack(acc1[2 * d + 1]);
        __nv_bfloat16 h4[4];
        __nv_bfloat16 l4[4];
        split1(p0.x * inv1, h4[0], l4[0]);
        split1(p0.y * inv1, h4[1], l4[1]);
        split1(p1.x * inv1, h4[2], l4[2]);
        split1(p1.y * inv1, h4[3], l4[3]);
        *(uint2*)(g_ahi + ob1 + d * 4) = *(uint2*)h4;
        *(uint2*)(g_alo + ob1 + d * 4) = *(uint2*)l4;
        float2 r0 = f2unpack(acc2q[2 * d]);
        float2 r1 = f2unpack(acc2q[2 * d + 1]);
        split1(r0.x * inv2, h4[0], l4[0]);
        split1(r0.y * inv2, h4[1], l4[1]);
        split1(r1.x * inv2, h4[2], l4[2]);
        split1(r1.y * inv2, h4[3], l4[3]);
        *(uint2*)(g_ahi + ob2 + d * 4) = *(uint2*)h4;
        *(uint2*)(g_alo + ob2 + d * 4) = *(uint2*)l4;
    }
}

// ---------------------------------------------------------------------------
extern "C" void kernel_launch(void* const* d_in, const int* in_sizes, int n_in,
                              void* d_out, int out_size) {
    const float* x   = (const float*)d_in[0];
    const float* Wq  = (const float*)d_in[1];
    const float* Wkv = (const float*)d_in[2];
    const float* Wo  = (const float*)d_in[3];
    const float* bo  = (const float*)d_in[4];
    const float* p1  = (const float*)d_in[5];
    const float* p2  = (const float*)d_in[6];
    float* out = (float*)d_out;

    prep_kernel<<<768, 256>>>(p1, p2, Wq, Wkv, Wo);
    split_x<<<2048, 256>>>(x);
    gemm_wmma<<<dim3(6, 512), 256>>>(0, (float*)0, (const float*)0);
    attn1_kernel<<<dim3(256, 4, 4), 64>>>();
    attn2_kernel<<<dim3(64, 4, 4), 256>>>();
    gemm_wmma<<<dim3(2, 512), 256>>>(1, out, bo);
}

// round 16
// speedup vs baseline: 1.6448x; 1.0494x over previous
#include <cuda_runtime.h>
#include <cuda_bf16.h>
#include <mma.h>
#include <math.h>

using namespace nvcuda;

#define NB    4
#define SS    128
#define CDIM  256
#define NHH   4
#define DHH   32
#define NWIN  256
#define WSZ   64
#define MTOT  (NB*SS*SS)
#define NQKV  768
#define QSCALE 0.17677669529663687f

typedef unsigned long long ull;

// ---------------- scratch ----------------
__device__ float g_q  [MTOT * CDIM];
__device__ float g_kv [MTOT * 2 * CDIM];
__device__ __nv_bfloat16 g_xhi[MTOT * CDIM];
__device__ __nv_bfloat16 g_xlo[MTOT * CDIM];
__device__ __nv_bfloat16 g_ahi[MTOT * CDIM];
__device__ __nv_bfloat16 g_alo[MTOT * CDIM];
__device__ __nv_bfloat16 g_whi[CDIM * NQKV];
__device__ __nv_bfloat16 g_wlo[CDIM * NQKV];
__device__ __nv_bfloat16 g_wohi[CDIM * CDIM];
__device__ __nv_bfloat16 g_wolo[CDIM * CDIM];
__device__ float g_pos1t[NHH * WSZ * WSZ];
__device__ float g_pos2t[NHH * NWIN * NWIN];

// ---------------- helpers (no braces inside asm strings) ----------------
union F2U {
    float2 f;
    ull u;
};
__device__ __forceinline__ ull f2pack(float x, float y) {
    F2U t; t.f = make_float2(x, y); return t.u;
}
__device__ __forceinline__ float2 f2unpack(ull v) {
    F2U t; t.u = v; return t.f;
}
__device__ __forceinline__ ull ffma2(ull a, ull b, ull c) {
    ull d;
    asm("fma.rn.f32x2 %0,%1,%2,%3;" : "=l"(d) : "l"(a), "l"(b), "l"(c));
    return d;
}
__device__ __forceinline__ ull fmul2(ull a, ull b) {
    ull d;
    asm("mul.rn.f32x2 %0,%1,%2;" : "=l"(d) : "l"(a), "l"(b));
    return d;
}
__device__ __forceinline__ void split1(float x, __nv_bfloat16& h, __nv_bfloat16& l) {
    h = __float2bfloat16(x);
    l = __float2bfloat16(x - __bfloat162float(h));
}
__device__ __forceinline__ void cpasync16(void* s, const void* g) {
    unsigned saddr = (unsigned)__cvta_generic_to_shared(s);
    asm volatile("cp.async.cg.shared.global [%0], [%1], 16;" :: "r"(saddr), "l"(g));
}
__device__ __forceinline__ void cpcommit() {
    asm volatile("cp.async.commit_group;");
}
__device__ __forceinline__ void cpwait0() {
    asm volatile("cp.async.wait_group 0;");
}
__device__ __forceinline__ void cpwait1() {
    asm volatile("cp.async.wait_group 1;");
}

// ---------------- merged prep: pos transposes + weight splits + x split -----
__global__ void prep_kernel(const float* __restrict__ p1,
                            const float* __restrict__ p2,
                            const float* __restrict__ Wq,
                            const float* __restrict__ Wkv,
                            const float* __restrict__ Wo,
                            const float* __restrict__ x) {
    int idx = blockIdx.x * blockDim.x + threadIdx.x;
    int stride = gridDim.x * blockDim.x;
    for (int i = idx; i < NHH * WSZ * WSZ; i += stride) {
        int hh = i / (WSZ * WSZ);
        int rem = i - hh * WSZ * WSZ;
        int r = rem / WSZ;
        int c = rem % WSZ;
        g_pos1t[(hh * WSZ + c) * WSZ + r] = p1[i];
    }
    for (int i = idx; i < NHH * NWIN * NWIN; i += stride) {
        int hh = i / (NWIN * NWIN);
        int rem = i - hh * NWIN * NWIN;
        int r = rem / NWIN;
        int c = rem % NWIN;
        g_pos2t[(hh * NWIN + c) * NWIN + r] = p2[i];
    }
    for (int i = idx; i < CDIM * CDIM; i += stride) {
        split1(Wo[i], g_wohi[i], g_wolo[i]);
    }
    for (int i = idx; i < CDIM * NQKV; i += stride) {
        int k = i / NQKV;
        int c = i % NQKV;
        float v = (c < 256) ? Wq[k * 256 + c] : Wkv[k * 512 + (c - 256)];
        split1(v, g_whi[i], g_wlo[i]);
    }
    const int n4 = MTOT * CDIM / 4;
    for (int i = idx; i < n4; i += stride) {
        float4 v = ((const float4*)x)[i];
        __nv_bfloat16 h4[4];
        __nv_bfloat16 l4[4];
        split1(v.x, h4[0], l4[0]);
        split1(v.y, h4[1], l4[1]);
        split1(v.z, h4[2], l4[2]);
        split1(v.w, h4[3], l4[3]);
        ((uint2*)g_xhi)[i] = *(uint2*)h4;
        ((uint2*)g_xlo)[i] = *(uint2*)l4;
    }
}

// ---------------- WMMA split-bf16 GEMM, cp.async double-buffered ------------
__device__ __forceinline__ int remap_row(int row) {
    int b = row >> 14;
    int n = (row >> 6) & 255;
    int m = row & 63;
    int h = ((n >> 4) << 3) + (m >> 3);
    int w = ((n & 15) << 3) + (m & 7);
    return (b << 14) + (h << 7) + w;
}

__global__ __launch_bounds__(256) void gemm_wmma(
    int mode, float* __restrict__ outp, const float* __restrict__ bo)
{
    const int Ntot = mode ? 256 : NQKV;
    const __nv_bfloat16* __restrict__ Ahi = mode ? g_ahi : g_xhi;
    const __nv_bfloat16* __restrict__ Alo = mode ? g_alo : g_xlo;
    const __nv_bfloat16* __restrict__ Bhi = mode ? g_wohi : g_whi;
    const __nv_bfloat16* __restrict__ Blo = mode ? g_wolo : g_wlo;

    __shared__ __align__(32) __nv_bfloat16 As[2][2][128][24];
    __shared__ __align__(32) __nv_bfloat16 Bs[2][2][16][136];

    const int tid = threadIdx.x;
    const int wid = tid >> 5;
    const int lane = tid & 31;
    const int nb0 = blockIdx.x * 128;
    const int mrow0 = blockIdx.y * 128;
    const int m0w = (wid & 3) * 32;
    const int n0w = (wid >> 2) * 64;

    wmma::fragment<wmma::accumulator, 16, 16, 16, float> cfrag[2][4];
#pragma unroll
    for (int mi = 0; mi < 2; mi++) {
#pragma unroll
        for (int ni = 0; ni < 4; ni++) {
            wmma::fill_fragment(cfrag[mi][ni], 0.0f);
        }
    }

    const int arow = tid >> 1;
    const int acol8 = (tid & 1) * 8;
    const int bkr = tid >> 4;
    const int bnc8 = (tid & 15) * 8;

    {
        cpasync16(&As[0][0][arow][acol8],
                  Ahi + (size_t)(mrow0 + arow) * 256 + acol8);
        cpasync16(&As[0][1][arow][acol8],
                  Alo + (size_t)(mrow0 + arow) * 256 + acol8);
        cpasync16(&Bs[0][0][bkr][bnc8],
                  Bhi + (size_t)(bkr) * Ntot + nb0 + bnc8);
        cpasync16(&Bs[0][1][bkr][bnc8],
                  Blo + (size_t)(bkr) * Ntot + nb0 + bnc8);
        cpcommit();
    }

    const int NT = 256 / 16;
    for (int t = 0; t < NT; t++) {
        int buf = t & 1;
        if (t + 1 < NT) {
            int kn = (t + 1) * 16;
            cpasync16(&As[1 - buf][0][arow][acol8],
                      Ahi + (size_t)(mrow0 + arow) * 256 + kn + acol8);
            cpasync16(&As[1 - buf][1][arow][acol8],
                      Alo + (size_t)(mrow0 + arow) * 256 + kn + acol8);
            cpasync16(&Bs[1 - buf][0][bkr][bnc8],
                      Bhi + (size_t)(kn + bkr) * Ntot + nb0 + bnc8);
            cpasync16(&Bs[1 - buf][1][bkr][bnc8],
                      Blo + (size_t)(kn + bkr) * Ntot + nb0 + bnc8);
            cpcommit();
            cpwait1();
        } else {
            cpwait0();
        }
        __syncthreads();

        wmma::fragment<wmma::matrix_a, 16, 16, 16, __nv_bfloat16, wmma::row_major> afh[2];
        wmma::fragment<wmma::matrix_a, 16, 16, 16, __nv_bfloat16, wmma::row_major> afl[2];
        wmma::load_matrix_sync(afh[0], &As[buf][0][m0w][0], 24);
        wmma::load_matrix_sync(afh[1], &As[buf][0][m0w + 16][0], 24);
        wmma::load_matrix_sync(afl[0], &As[buf][1][m0w][0], 24);
        wmma::load_matrix_sync(afl[1], &As[buf][1][m0w + 16][0], 24);
#pragma unroll
        for (int ni = 0; ni < 4; ni++) {
            wmma::fragment<wmma::matrix_b, 16, 16, 16, __nv_bfloat16, wmma::row_major> bfh;
            wmma::fragment<wmma::matrix_b, 16, 16, 16, __nv_bfloat16, wmma::row_major> bfl;
            wmma::load_matrix_sync(bfh, &Bs[buf][0][0][n0w + ni * 16], 136);
            wmma::load_matrix_sync(bfl, &Bs[buf][1][0][n0w + ni * 16], 136);
#pragma unroll
            for (int mi = 0; mi < 2; mi++) {
                wmma::mma_sync(cfrag[mi][ni], afh[mi], bfh, cfrag[mi][ni]);
                wmma::mma_sync(cfrag[mi][ni], afh[mi], bfl, cfrag[mi][ni]);
                wmma::mma_sync(cfrag[mi][ni], afl[mi], bfh, cfrag[mi][ni]);
            }
        }
        __syncthreads();
    }

    if (mode == 0) {
#pragma unroll
        for (int mi = 0; mi < 2; mi++) {
#pragma unroll
            for (int ni = 0; ni < 4; ni++) {
                int row = mrow0 + m0w + mi * 16;
                int col = nb0 + n0w + ni * 16;
                if (col < 256) {
#pragma unroll
                    for (int e = 0; e < cfrag[mi][ni].num_elements; e++) {
                        cfrag[mi][ni].x[e] *= QSCALE;
                    }
                    wmma::store_matrix_sync(g_q + (size_t)row * 256 + col,
                                            cfrag[mi][ni], 256, wmma::mem_row_major);
                } else {
                    wmma::store_matrix_sync(g_kv + (size_t)row * 512 + (col - 256),
                                            cfrag[mi][ni], 512, wmma::mem_row_major);
                }
            }
        }
    } else {
        float* stg = (float*)&As[0][0][0][0];
        float* mystg = stg + wid * 256;
#pragma unroll
        for (int mi = 0; mi < 2; mi++) {
#pragma unroll
            for (int ni = 0; ni < 4; ni++) {
                wmma::store_matrix_sync(mystg, cfrag[mi][ni], 16, wmma::mem_row_major);
                __syncwarp();
                int row0 = mrow0 + m0w + mi * 16;
                int col0 = nb0 + n0w + ni * 16;
#pragma unroll
                for (int e = 0; e < 8; e++) {
                    int idx = lane * 8 + e;
                    int r = idx >> 4;
                    int c = idx & 15;
                    int grow = remap_row(row0 + r);
                    outp[(size_t)grow * 256 + col0 + c] = mystg[r * 16 + c] + bo[col0 + c];
                }
                __syncwarp();
            }
        }
    }
}

// ---------------- attention branch 1 (within-window, seq=64) ----------------
__global__ __launch_bounds__(64) void attn1_kernel() {
    int n  = blockIdx.x;
    int hh = blockIdx.y;
    int b  = blockIdx.z;
    int i  = threadIdx.x;

    __shared__ float ks[WSZ][36];
    __shared__ float vs[WSZ][36];

    int h = ((n >> 4) << 3) + (i >> 3);
    int w = ((n & 15) << 3) + (i & 7);
    size_t grow = ((size_t)b << 14) + (h << 7) + w;

    {
        const float4* kp = (const float4*)(g_kv + grow * 512 + hh * DHH);
        const float4* vp = (const float4*)(g_kv + grow * 512 + 256 + hh * DHH);
#pragma unroll
        for (int d4 = 0; d4 < 8; d4++) {
            *(float4*)(&ks[i][d4 * 4]) = kp[d4];
            *(float4*)(&vs[i][d4 * 4]) = vp[d4];
        }
    }
    ull qr2[16];
    {
        const ulonglong2* qp = (const ulonglong2*)(g_q + grow * 256 + hh * DHH);
#pragma unroll
        for (int d4 = 0; d4 < 8; d4++) {
            ulonglong2 q4 = qp[d4];
            qr2[2 * d4]     = q4.x;
            qr2[2 * d4 + 1] = q4.y;
        }
    }
    __syncthreads();

    const float* pos = g_pos1t + hh * WSZ * WSZ;
    float mrun = -INFINITY;
    float l = 0.f;
    ull acc2[16];
#pragma unroll
    for (int t = 0; t < 16; t++) acc2[t] = 0ULL;

#pragma unroll 2
    for (int j = 0; j < WSZ; j++) {
        float pb = pos[j * WSZ + i];
        const ulonglong2* kp2 = (const ulonglong2*)(&ks[j][0]);
        ull s2 = 0ULL;
#pragma unroll
        for (int t = 0; t < 8; t++) {
            ulonglong2 kk = kp2[t];
            s2 = ffma2(qr2[2 * t], kk.x, s2);
            s2 = ffma2(qr2[2 * t + 1], kk.y, s2);
        }
        float2 sv = f2unpack(s2);
        float s = sv.x + sv.y + pb;
        if (s > mrun) {
            float c = __expf(mrun - s);
            mrun = s;
            l *= c;
            ull cc2 = f2pack(c, c);
#pragma unroll
            for (int t = 0; t < 16; t++) acc2[t] = fmul2(acc2[t], cc2);
        }
        float p = __expf(s - mrun);
        l += p;
        ull pp2 = f2pack(p, p);
        const ulonglong2* vp2 = (const ulonglong2*)(&vs[j][0]);
#pragma unroll
        for (int t = 0; t < 8; t++) {
            ulonglong2 vv = vp2[t];
            acc2[2 * t]     = ffma2(pp2, vv.x, acc2[2 * t]);
            acc2[2 * t + 1] = ffma2(pp2, vv.y, acc2[2 * t + 1]);
        }
    }
    float inv = 1.f / l;
    size_t obase = (((size_t)(b * NWIN + n) * WSZ) + i) * CDIM + hh * DHH;
#pragma unroll
    for (int t = 0; t < 8; t++) {
        float2 p0 = f2unpack(acc2[2 * t]);
        float2 p1 = f2unpack(acc2[2 * t + 1]);
        __nv_bfloat16 h4[4];
        __nv_bfloat16 l4[4];
        split1(p0.x * inv, h4[0], l4[0]);
        split1(p0.y * inv, h4[1], l4[1]);
        split1(p1.x * inv, h4[2], l4[2]);
        split1(p1.y * inv, h4[3], l4[3]);
        *(uint2*)(g_ahi + obase + t * 4) = *(uint2*)h4;
        *(uint2*)(g_alo + obase + t * 4) = *(uint2*)l4;
    }
}

// ---------------- attention branch 2 (cross-window, seq=256) ----------------
// 128 threads, 2048 blocks: block = (m, query half). Better waves + warps/SM.
__global__ void attn2_kernel() {
    int m  = blockIdx.x >> 1;
    int qh = blockIdx.x & 1;
    int hh = blockIdx.y;
    int b  = blockIdx.z;
    int t  = threadIdx.x;           // 0..127
    int i  = qh * 128 + t;          // query index 0..255

    __shared__ float ks[128][36];
    __shared__ float vs[128][36];

    int h = ((i >> 4) << 3) + (m >> 3);
    int w = ((i & 15) << 3) + (m & 7);
    size_t grow = ((size_t)b << 14) + (h << 7) + w;

    ull qr2[16];
    {
        const ulonglong2* qp = (const ulonglong2*)(g_q + grow * 256 + 128 + hh * DHH);
#pragma unroll
        for (int d4 = 0; d4 < 8; d4++) {
            ulonglong2 q4 = qp[d4];
            qr2[2 * d4]     = q4.x;
            qr2[2 * d4 + 1] = q4.y;
        }
    }

    const float* pos = g_pos2t + hh * NWIN * NWIN;
    float mrun = -INFINITY;
    float l = 0.f;
    ull acc2[16];
#pragma unroll
    for (int t2 = 0; t2 < 16; t2++) acc2[t2] = 0ULL;

    for (int jc = 0; jc < NWIN; jc += 128) {
        __syncthreads();
        {
            int r = t;
            int jw = jc + r;
            int hK = ((jw >> 4) << 3) + (m >> 3);
            int wK = ((jw & 15) << 3) + (m & 7);
            size_t gk = ((size_t)b << 14) + (hK << 7) + wK;
            const float4* kp = (const float4*)(g_kv + gk * 512 + 128 + hh * DHH);
            const float4* vp = (const float4*)(g_kv + gk * 512 + 384 + hh * DHH);
#pragma unroll
            for (int d4 = 0; d4 < 8; d4++) {
                *(float4*)(&ks[r][d4 * 4]) = kp[d4];
                *(float4*)(&vs[r][d4 * 4]) = vp[d4];
            }
        }
        __syncthreads();

#pragma unroll 2
        for (int jj = 0; jj < 128; jj++) {
            float pb = pos[(jc + jj) * NWIN + i];
            const ulonglong2* kp2 = (const ulonglong2*)(&ks[jj][0]);
            ull s2 = 0ULL;
#pragma unroll
            for (int u = 0; u < 8; u++) {
                ulonglong2 kk = kp2[u];
                s2 = ffma2(qr2[2 * u], kk.x, s2);
                s2 = ffma2(qr2[2 * u + 1], kk.y, s2);
            }
            float2 sv = f2unpack(s2);
            float s = sv.x + sv.y + pb;
            if (s > mrun) {
                float c = __expf(mrun - s);
                mrun = s;
                l *= c;
                ull cc2 = f2pack(c, c);
#pragma unroll
                for (int u = 0; u < 16; u++) acc2[u] = fmul2(acc2[u], cc2);
            }
            float p = __expf(s - mrun);
            l += p;
            ull pp2 = f2pack(p, p);
            const ulonglong2* vp2 = (const ulonglong2*)(&vs[jj][0]);
#pragma unroll
            for (int u = 0; u < 8; u++) {
                ulonglong2 vv = vp2[u];
                acc2[2 * u]     = ffma2(pp2, vv.x, acc2[2 * u]);
                acc2[2 * u + 1] = ffma2(pp2, vv.y, acc2[2 * u + 1]);
            }
        }
    }
    float inv = 1.f / l;
    size_t obase = (((size_t)(b * NWIN + i) * WSZ) + m) * CDIM + 128 + hh * DHH;
#pragma unroll
    for (int u = 0; u < 8; u++) {
        float2 p0 = f2unpack(acc2[2 * u]);
        float2 p1 = f2unpack(acc2[2 * u + 1]);
        __nv_bfloat16 h4[4];
        __nv_bfloat16 l4[4];
        split1(p0.x * inv, h4[0], l4[0]);
        split1(p0.y * inv, h4[1], l4[1]);
        split1(p1.x * inv, h4[2], l4[2]);
        split1(p1.y * inv, h4[3], l4[3]);
        *(uint2*)(g_ahi + obase + u * 4) = *(uint2*)h4;
        *(uint2*)(g_alo + obase + u * 4) = *(uint2*)l4;
    }
}

// ---------------------------------------------------------------------------
extern "C" void kernel_launch(void* const* d_in, const int* in_sizes, int n_in,
                              void* d_out, int out_size) {
    const float* x   = (const float*)d_in[0];
    const float* Wq  = (const float*)d_in[1];
    const float* Wkv = (const float*)d_in[2];
    const float* Wo  = (const float*)d_in[3];
    const float* bo  = (const float*)d_in[4];
    const float* p1  = (const float*)d_in[5];
    const float* p2  = (const float*)d_in[6];
    float* out = (float*)d_out;

    prep_kernel<<<2048, 256>>>(p1, p2, Wq, Wkv, Wo, x);
    gemm_wmma<<<dim3(6, 512), 256>>>(0, (float*)0, (const float*)0);
    attn1_kernel<<<dim3(256, 4, 4), 64>>>();
    attn2_kernel<<<dim3(128, 4, 4), 128>>>();
    gemm_wmma<<<dim3(2, 512), 256>>>(1, out, bo);
}

// round 17
// speedup vs baseline: 1.6718x; 1.0164x over previous
#include <cuda_runtime.h>
#include <cuda_bf16.h>
#include <mma.h>
#include <math.h>

using namespace nvcuda;

#define NB    4
#define SS    128
#define CDIM  256
#define NHH   4
#define DHH   32
#define NWIN  256
#define WSZ   64
#define MTOT  (NB*SS*SS)
#define NQKV  768
#define QSCALE 0.17677669529663687f

typedef unsigned long long ull;

// ---------------- scratch ----------------
__device__ float g_q  [MTOT * CDIM];
__device__ float g_kv [MTOT * 2 * CDIM];
__device__ __nv_bfloat16 g_xhi[MTOT * CDIM];
__device__ __nv_bfloat16 g_xlo[MTOT * CDIM];
__device__ __nv_bfloat16 g_ahi[MTOT * CDIM];
__device__ __nv_bfloat16 g_alo[MTOT * CDIM];
__device__ __nv_bfloat16 g_whi[CDIM * NQKV];
__device__ __nv_bfloat16 g_wlo[CDIM * NQKV];
__device__ __nv_bfloat16 g_wohi[CDIM * CDIM];
__device__ __nv_bfloat16 g_wolo[CDIM * CDIM];
__device__ float g_pos1t[NHH * WSZ * WSZ];
__device__ float g_pos2t[NHH * NWIN * NWIN];

// ---------------- helpers (no braces inside asm strings) ----------------
union F2U {
    float2 f;
    ull u;
};
__device__ __forceinline__ ull f2pack(float x, float y) {
    F2U t; t.f = make_float2(x, y); return t.u;
}
__device__ __forceinline__ float2 f2unpack(ull v) {
    F2U t; t.u = v; return t.f;
}
__device__ __forceinline__ ull ffma2(ull a, ull b, ull c) {
    ull d;
    asm("fma.rn.f32x2 %0,%1,%2,%3;" : "=l"(d) : "l"(a), "l"(b), "l"(c));
    return d;
}
__device__ __forceinline__ ull fmul2(ull a, ull b) {
    ull d;
    asm("mul.rn.f32x2 %0,%1,%2;" : "=l"(d) : "l"(a), "l"(b));
    return d;
}
__device__ __forceinline__ void split1(float x, __nv_bfloat16& h, __nv_bfloat16& l) {
    h = __float2bfloat16(x);
    l = __float2bfloat16(x - __bfloat162float(h));
}
__device__ __forceinline__ void cpasync16(void* s, const void* g) {
    unsigned saddr = (unsigned)__cvta_generic_to_shared(s);
    asm volatile("cp.async.cg.shared.global [%0], [%1], 16;" :: "r"(saddr), "l"(g));
}
__device__ __forceinline__ void cpcommit() {
    asm volatile("cp.async.commit_group;");
}
__device__ __forceinline__ void cpwait0() {
    asm volatile("cp.async.wait_group 0;");
}
__device__ __forceinline__ void cpwait1() {
    asm volatile("cp.async.wait_group 1;");
}

// ---------------- merged prep: pos transposes + weight splits + x split -----
__global__ void prep_kernel(const float* __restrict__ p1,
                            const float* __restrict__ p2,
                            const float* __restrict__ Wq,
                            const float* __restrict__ Wkv,
                            const float* __restrict__ Wo,
                            const float* __restrict__ x) {
    int idx = blockIdx.x * blockDim.x + threadIdx.x;
    int stride = gridDim.x * blockDim.x;
    for (int i = idx; i < NHH * WSZ * WSZ; i += stride) {
        int hh = i / (WSZ * WSZ);
        int rem = i - hh * WSZ * WSZ;
        int r = rem / WSZ;
        int c = rem % WSZ;
        g_pos1t[(hh * WSZ + c) * WSZ + r] = p1[i];
    }
    for (int i = idx; i < NHH * NWIN * NWIN; i += stride) {
        int hh = i / (NWIN * NWIN);
        int rem = i - hh * NWIN * NWIN;
        int r = rem / NWIN;
        int c = rem % NWIN;
        g_pos2t[(hh * NWIN + c) * NWIN + r] = p2[i];
    }
    for (int i = idx; i < CDIM * CDIM; i += stride) {
        split1(Wo[i], g_wohi[i], g_wolo[i]);
    }
    for (int i = idx; i < CDIM * NQKV; i += stride) {
        int k = i / NQKV;
        int c = i % NQKV;
        float v = (c < 256) ? Wq[k * 256 + c] : Wkv[k * 512 + (c - 256)];
        split1(v, g_whi[i], g_wlo[i]);
    }
    const int n4 = MTOT * CDIM / 4;
    for (int i = idx; i < n4; i += stride) {
        float4 v = ((const float4*)x)[i];
        __nv_bfloat16 h4[4];
        __nv_bfloat16 l4[4];
        split1(v.x, h4[0], l4[0]);
        split1(v.y, h4[1], l4[1]);
        split1(v.z, h4[2], l4[2]);
        split1(v.w, h4[3], l4[3]);
        ((uint2*)g_xhi)[i] = *(uint2*)h4;
        ((uint2*)g_xlo)[i] = *(uint2*)l4;
    }
}

// ---------------- WMMA split-bf16 GEMM, cp.async double-buffered ------------
__device__ __forceinline__ int remap_row(int row) {
    int b = row >> 14;
    int n = (row >> 6) & 255;
    int m = row & 63;
    int h = ((n >> 4) << 3) + (m >> 3);
    int w = ((n & 15) << 3) + (m & 7);
    return (b << 14) + (h << 7) + w;
}

__global__ __launch_bounds__(256) void gemm_wmma(
    int mode, float* __restrict__ outp, const float* __restrict__ bo)
{
    const int Ntot = mode ? 256 : NQKV;
    const __nv_bfloat16* __restrict__ Ahi = mode ? g_ahi : g_xhi;
    const __nv_bfloat16* __restrict__ Alo = mode ? g_alo : g_xlo;
    const __nv_bfloat16* __restrict__ Bhi = mode ? g_wohi : g_whi;
    const __nv_bfloat16* __restrict__ Blo = mode ? g_wolo : g_wlo;

    __shared__ __align__(32) __nv_bfloat16 As[2][2][128][24];
    __shared__ __align__(32) __nv_bfloat16 Bs[2][2][16][136];

    const int tid = threadIdx.x;
    const int wid = tid >> 5;
    const int lane = tid & 31;
    const int nb0 = blockIdx.x * 128;
    const int mrow0 = blockIdx.y * 128;
    const int m0w = (wid & 3) * 32;
    const int n0w = (wid >> 2) * 64;

    wmma::fragment<wmma::accumulator, 16, 16, 16, float> cfrag[2][4];
#pragma unroll
    for (int mi = 0; mi < 2; mi++) {
#pragma unroll
        for (int ni = 0; ni < 4; ni++) {
            wmma::fill_fragment(cfrag[mi][ni], 0.0f);
        }
    }

    const int arow = tid >> 1;
    const int acol8 = (tid & 1) * 8;
    const int bkr = tid >> 4;
    const int bnc8 = (tid & 15) * 8;

    {
        cpasync16(&As[0][0][arow][acol8],
                  Ahi + (size_t)(mrow0 + arow) * 256 + acol8);
        cpasync16(&As[0][1][arow][acol8],
                  Alo + (size_t)(mrow0 + arow) * 256 + acol8);
        cpasync16(&Bs[0][0][bkr][bnc8],
                  Bhi + (size_t)(bkr) * Ntot + nb0 + bnc8);
        cpasync16(&Bs[0][1][bkr][bnc8],
                  Blo + (size_t)(bkr) * Ntot + nb0 + bnc8);
        cpcommit();
    }

    const int NT = 256 / 16;
    for (int t = 0; t < NT; t++) {
        int buf = t & 1;
        if (t + 1 < NT) {
            int kn = (t + 1) * 16;
            cpasync16(&As[1 - buf][0][arow][acol8],
                      Ahi + (size_t)(mrow0 + arow) * 256 + kn + acol8);
            cpasync16(&As[1 - buf][1][arow][acol8],
                      Alo + (size_t)(mrow0 + arow) * 256 + kn + acol8);
            cpasync16(&Bs[1 - buf][0][bkr][bnc8],
                      Bhi + (size_t)(kn + bkr) * Ntot + nb0 + bnc8);
            cpasync16(&Bs[1 - buf][1][bkr][bnc8],
                      Blo + (size_t)(kn + bkr) * Ntot + nb0 + bnc8);
            cpcommit();
            cpwait1();
        } else {
            cpwait0();
        }
        __syncthreads();

        wmma::fragment<wmma::matrix_a, 16, 16, 16, __nv_bfloat16, wmma::row_major> afh[2];
        wmma::fragment<wmma::matrix_a, 16, 16, 16, __nv_bfloat16, wmma::row_major> afl[2];
        wmma::load_matrix_sync(afh[0], &As[buf][0][m0w][0], 24);
        wmma::load_matrix_sync(afh[1], &As[buf][0][m0w + 16][0], 24);
        wmma::load_matrix_sync(afl[0], &As[buf][1][m0w][0], 24);
        wmma::load_matrix_sync(afl[1], &As[buf][1][m0w + 16][0], 24);
#pragma unroll
        for (int ni = 0; ni < 4; ni++) {
            wmma::fragment<wmma::matrix_b, 16, 16, 16, __nv_bfloat16, wmma::row_major> bfh;
            wmma::fragment<wmma::matrix_b, 16, 16, 16, __nv_bfloat16, wmma::row_major> bfl;
            wmma::load_matrix_sync(bfh, &Bs[buf][0][0][n0w + ni * 16], 136);
            wmma::load_matrix_sync(bfl, &Bs[buf][1][0][n0w + ni * 16], 136);
#pragma unroll
            for (int mi = 0; mi < 2; mi++) {
                wmma::mma_sync(cfrag[mi][ni], afh[mi], bfh, cfrag[mi][ni]);
                wmma::mma_sync(cfrag[mi][ni], afh[mi], bfl, cfrag[mi][ni]);
                wmma::mma_sync(cfrag[mi][ni], afl[mi], bfh, cfrag[mi][ni]);
            }
        }
        __syncthreads();
    }

    if (mode == 0) {
#pragma unroll
        for (int mi = 0; mi < 2; mi++) {
#pragma unroll
            for (int ni = 0; ni < 4; ni++) {
                int row = mrow0 + m0w + mi * 16;
                int col = nb0 + n0w + ni * 16;
                if (col < 256) {
#pragma unroll
                    for (int e = 0; e < cfrag[mi][ni].num_elements; e++) {
                        cfrag[mi][ni].x[e] *= QSCALE;
                    }
                    wmma::store_matrix_sync(g_q + (size_t)row * 256 + col,
                                            cfrag[mi][ni], 256, wmma::mem_row_major);
                } else {
                    wmma::store_matrix_sync(g_kv + (size_t)row * 512 + (col - 256),
                                            cfrag[mi][ni], 512, wmma::mem_row_major);
                }
            }
        }
    } else {
        float* stg = (float*)&As[0][0][0][0];
        float* mystg = stg + wid * 256;
#pragma unroll
        for (int mi = 0; mi < 2; mi++) {
#pragma unroll
            for (int ni = 0; ni < 4; ni++) {
                wmma::store_matrix_sync(mystg, cfrag[mi][ni], 16, wmma::mem_row_major);
                __syncwarp();
                int row0 = mrow0 + m0w + mi * 16;
                int col0 = nb0 + n0w + ni * 16;
#pragma unroll
                for (int e = 0; e < 8; e++) {
                    int idx = lane * 8 + e;
                    int r = idx >> 4;
                    int c = idx & 15;
                    int grow = remap_row(row0 + r);
                    outp[(size_t)grow * 256 + col0 + c] = mystg[r * 16 + c] + bo[col0 + c];
                }
                __syncwarp();
            }
        }
    }
}

// ---------------- attention branch 1 (within-window, seq=64) ----------------
__global__ __launch_bounds__(64) void attn1_kernel() {
    int n  = blockIdx.x;
    int hh = blockIdx.y;
    int b  = blockIdx.z;
    int i  = threadIdx.x;

    __shared__ float ks[WSZ][36];
    __shared__ float vs[WSZ][36];

    int h = ((n >> 4) << 3) + (i >> 3);
    int w = ((n & 15) << 3) + (i & 7);
    size_t grow = ((size_t)b << 14) + (h << 7) + w;

    {
        const float4* kp = (const float4*)(g_kv + grow * 512 + hh * DHH);
        const float4* vp = (const float4*)(g_kv + grow * 512 + 256 + hh * DHH);
#pragma unroll
        for (int d4 = 0; d4 < 8; d4++) {
            *(float4*)(&ks[i][d4 * 4]) = kp[d4];
            *(float4*)(&vs[i][d4 * 4]) = vp[d4];
        }
    }
    ull qr2[16];
    {
        const ulonglong2* qp = (const ulonglong2*)(g_q + grow * 256 + hh * DHH);
#pragma unroll
        for (int d4 = 0; d4 < 8; d4++) {
            ulonglong2 q4 = qp[d4];
            qr2[2 * d4]     = q4.x;
            qr2[2 * d4 + 1] = q4.y;
        }
    }
    __syncthreads();

    const float* pos = g_pos1t + hh * WSZ * WSZ;
    float mrun = -INFINITY;
    float l = 0.f;
    ull acc2[16];
#pragma unroll
    for (int t = 0; t < 16; t++) acc2[t] = 0ULL;

#pragma unroll 2
    for (int j = 0; j < WSZ; j++) {
        float pb = pos[j * WSZ + i];
        const ulonglong2* kp2 = (const ulonglong2*)(&ks[j][0]);
        ull s2 = 0ULL;
#pragma unroll
        for (int t = 0; t < 8; t++) {
            ulonglong2 kk = kp2[t];
            s2 = ffma2(qr2[2 * t], kk.x, s2);
            s2 = ffma2(qr2[2 * t + 1], kk.y, s2);
        }
        float2 sv = f2unpack(s2);
        float s = sv.x + sv.y + pb;
        if (s > mrun) {
            float c = __expf(mrun - s);
            mrun = s;
            l *= c;
            ull cc2 = f2pack(c, c);
#pragma unroll
            for (int t = 0; t < 16; t++) acc2[t] = fmul2(acc2[t], cc2);
        }
        float p = __expf(s - mrun);
        l += p;
        ull pp2 = f2pack(p, p);
        const ulonglong2* vp2 = (const ulonglong2*)(&vs[j][0]);
#pragma unroll
        for (int t = 0; t < 8; t++) {
            ulonglong2 vv = vp2[t];
            acc2[2 * t]     = ffma2(pp2, vv.x, acc2[2 * t]);
            acc2[2 * t + 1] = ffma2(pp2, vv.y, acc2[2 * t + 1]);
        }
    }
    float inv = 1.f / l;
    size_t obase = (((size_t)(b * NWIN + n) * WSZ) + i) * CDIM + hh * DHH;
#pragma unroll
    for (int t = 0; t < 8; t++) {
        float2 p0 = f2unpack(acc2[2 * t]);
        float2 p1 = f2unpack(acc2[2 * t + 1]);
        __nv_bfloat16 h4[4];
        __nv_bfloat16 l4[4];
        split1(p0.x * inv, h4[0], l4[0]);
        split1(p0.y * inv, h4[1], l4[1]);
        split1(p1.x * inv, h4[2], l4[2]);
        split1(p1.y * inv, h4[3], l4[3]);
        *(uint2*)(g_ahi + obase + t * 4) = *(uint2*)h4;
        *(uint2*)(g_alo + obase + t * 4) = *(uint2*)l4;
    }
}

// ---------------- attention branch 2 (cross-window, seq=256) ----------------
__global__ __launch_bounds__(256) void attn2_kernel() {
    int m  = blockIdx.x;
    int hh = blockIdx.y;
    int b  = blockIdx.z;
    int i  = threadIdx.x;

    __shared__ float ks[128][36];
    __shared__ float vs[128][36];

    int h = ((i >> 4) << 3) + (m >> 3);
    int w = ((i & 15) << 3) + (m & 7);
    size_t grow = ((size_t)b << 14) + (h << 7) + w;

    ull qr2[16];
    {
        const ulonglong2* qp = (const ulonglong2*)(g_q + grow * 256 + 128 + hh * DHH);
#pragma unroll
        for (int d4 = 0; d4 < 8; d4++) {
            ulonglong2 q4 = qp[d4];
            qr2[2 * d4]     = q4.x;
            qr2[2 * d4 + 1] = q4.y;
        }
    }

    const float* pos = g_pos2t + hh * NWIN * NWIN;
    float mrun = -INFINITY;
    float l = 0.f;
    ull acc2[16];
#pragma unroll
    for (int t = 0; t < 16; t++) acc2[t] = 0ULL;

    for (int jc = 0; jc < NWIN; jc += 128) {
        __syncthreads();
        {
            int t = threadIdx.x;
            int r = t & 127;
            int jw = jc + r;
            int hK = ((jw >> 4) << 3) + (m >> 3);
            int wK = ((jw & 15) << 3) + (m & 7);
            size_t gk = ((size_t)b << 14) + (hK << 7) + wK;
            if (t < 128) {
                const float4* kp = (const float4*)(g_kv + gk * 512 + 128 + hh * DHH);
#pragma unroll
                for (int d4 = 0; d4 < 8; d4++) *(float4*)(&ks[r][d4 * 4]) = kp[d4];
            } else {
                const float4* vp = (const float4*)(g_kv + gk * 512 + 384 + hh * DHH);
#pragma unroll
                for (int d4 = 0; d4 < 8; d4++) *(float4*)(&vs[r][d4 * 4]) = vp[d4];
            }
        }
        __syncthreads();

#pragma unroll 2
        for (int jj = 0; jj < 128; jj++) {
            float pb = pos[(jc + jj) * NWIN + i];
            const ulonglong2* kp2 = (const ulonglong2*)(&ks[jj][0]);
            ull s2 = 0ULL;
#pragma unroll
            for (int t = 0; t < 8; t++) {
                ulonglong2 kk = kp2[t];
                s2 = ffma2(qr2[2 * t], kk.x, s2);
                s2 = ffma2(qr2[2 * t + 1], kk.y, s2);
            }
            float2 sv = f2unpack(s2);
            float s = sv.x + sv.y + pb;
            if (s > mrun) {
                float c = __expf(mrun - s);
                mrun = s;
                l *= c;
                ull cc2 = f2pack(c, c);
#pragma unroll
                for (int t = 0; t < 16; t++) acc2[t] = fmul2(acc2[t], cc2);
            }
            float p = __expf(s - mrun);
            l += p;
            ull pp2 = f2pack(p, p);
            const ulonglong2* vp2 = (const ulonglong2*)(&vs[jj][0]);
#pragma unroll
            for (int t = 0; t < 8; t++) {
                ulonglong2 vv = vp2[t];
                acc2[2 * t]     = ffma2(pp2, vv.x, acc2[2 * t]);
                acc2[2 * t + 1] = ffma2(pp2, vv.y, acc2[2 * t + 1]);
            }
        }
    }
    float inv = 1.f / l;
    size_t obase = (((size_t)(b * NWIN + i) * WSZ) + m) * CDIM + 128 + hh * DHH;
#pragma unroll
    for (int t = 0; t < 8; t++) {
        float2 p0 = f2unpack(acc2[2 * t]);
        float2 p1 = f2unpack(acc2[2 * t + 1]);
        __nv_bfloat16 h4[4];
        __nv_bfloat16 l4[4];
        split1(p0.x * inv, h4[0], l4[0]);
        split1(p0.y * inv, h4[1], l4[1]);
        split1(p1.x * inv, h4[2], l4[2]);
        split1(p1.y * inv, h4[3], l4[3]);
        *(uint2*)(g_ahi + obase + t * 4) = *(uint2*)h4;
        *(uint2*)(g_alo + obase + t * 4) = *(uint2*)l4;
    }
}

// ---------------------------------------------------------------------------
extern "C" void kernel_launch(void* const* d_in, const int* in_sizes, int n_in,
                              void* d_out, int out_size) {
    const float* x   = (const float*)d_in[0];
    const float* Wq  = (const float*)d_in[1];
    const float* Wkv = (const float*)d_in[2];
    const float* Wo  = (const float*)d_in[3];
    const float* bo  = (const float*)d_in[4];
    const float* p1  = (const float*)d_in[5];
    const float* p2  = (const float*)d_in[6];
    float* out = (float*)d_out;

    prep_kernel<<<2048, 256>>>(p1, p2, Wq, Wkv, Wo, x);
    gemm_wmma<<<dim3(6, 512), 256>>>(0, (float*)0, (const float*)0);
    attn1_kernel<<<dim3(256, 4, 4), 64>>>();
    attn2_kernel<<<dim3(64, 4, 4), 256>>>();
    gemm_wmma<<<dim3(2, 512), 256>>>(1, out, bo);
}